// round 5
// baseline (speedup 1.0000x reference)
#include <cuda_runtime.h>
#include <cuda_bf16.h>

#define N_PRED 2048
#define T_RUNS 16
#define M_BOX  2048
#define EPS_F  1e-7f

#define GB      16
#define NBINS   (GB*GB)
#define BIN_ORG (-28.0f)
#define BIN_INV (1.0f/42.0f)
#define WH_MAX  55.0f          // box w,h in [5,55)
#define CAP     1280           // smem slab capacity (5 rows avg ~640)

// ---- device scratch (no allocations allowed) ----
__device__ float4 g_sbox[T_RUNS][M_BOX];      // binned boxes (x1,y1,x2,y2)
__device__ float  g_snarea[T_RUNS][M_BOX];    // -(areaB), binned order
__device__ int    g_bstart[T_RUNS][NBINS+1];  // box bin prefix offsets per run
__device__ float4 g_pbox[N_PRED];             // pred boxes, bin-sorted
__device__ int    g_perm[N_PRED];             // sorted slot -> original pred idx
__device__ int    g_pstart[NBINS+1];          // pred bin prefix offsets

__device__ __forceinline__ int bin1d(float v) {
    int b = (int)floorf((v - BIN_ORG) * BIN_INV);
    return min(max(b, 0), GB - 1);
}

// ---------------------------------------------------------------------------
// prep: blocks 0..15 counting-sort run t's boxes; block 16 sorts preds,
// writes g_pstart, zeroes out. 256 threads == NBINS. Raw rows are staged
// through smem with coalesced float4 loads (the stride-6 scalar gather in R4
// was the latency bottleneck).
// ---------------------------------------------------------------------------
__global__ __launch_bounds__(256)
void prep_kernel(const float* __restrict__ pred,
                 const float* __restrict__ dropout_preds,
                 float* __restrict__ out)
{
    __shared__ float4 stage4[1536];           // 24 KB: 1024 boxes x 6 floats
    __shared__ int cnt[NBINS];
    __shared__ int wsum[8];
    float* stage = (float*)stage4;

    const int tid  = threadIdx.x;
    const int lane = tid & 31, wid = tid >> 5;
    const bool is_box_block = (blockIdx.x < T_RUNS);
    const float* srcbase = is_box_block
        ? dropout_preds + (size_t)blockIdx.x * M_BOX * 6
        : pred;

    cnt[tid] = 0;
    if (!is_box_block) {
        #pragma unroll
        for (int k = 0; k < 8; ++k) out[tid + k * 256] = 0.0f;  // out poisoned
    }
    __syncthreads();

    // ---- count (two 1024-box halves, staged coalesced) ----
    float4 box[8];
    int    bin[8];
    #pragma unroll
    for (int half = 0; half < 2; ++half) {
        const float4* s4 = reinterpret_cast<const float4*>(srcbase) + half * 1536;
        #pragma unroll
        for (int i = 0; i < 6; ++i) stage4[tid + i * 256] = s4[tid + i * 256];
        __syncthreads();
        #pragma unroll
        for (int k = 0; k < 4; ++k) {
            const float* s = stage + (tid + k * 256) * 6;
            const int j = half * 4 + k;
            box[j] = make_float4(s[0], s[1], s[2], s[3]);
            bin[j] = bin1d(s[1]) * GB + bin1d(s[0]);
            atomicAdd(&cnt[bin[j]], 1);
        }
        __syncthreads();
    }

    // ---- exclusive scan over 256 bins (shfl + 8-way combine) ----
    int v = cnt[tid];
    int inc = v;
    #pragma unroll
    for (int o = 1; o < 32; o <<= 1) {
        int n = __shfl_up_sync(0xffffffffu, inc, o);
        if (lane >= o) inc += n;
    }
    if (lane == 31) wsum[wid] = inc;
    __syncthreads();
    if (wid == 0) {
        int w = (lane < 8) ? wsum[lane] : 0;
        int wi = w;
        #pragma unroll
        for (int o = 1; o < 8; o <<= 1) {
            int n = __shfl_up_sync(0xffffffffu, wi, o);
            if (lane >= o) wi += n;
        }
        if (lane < 8) wsum[lane] = wi - w;
    }
    __syncthreads();
    const int start = inc - v + wsum[wid];
    cnt[tid] = start;
    __syncthreads();

    // ---- scatter ----
    if (is_box_block) {
        const int t = blockIdx.x;
        g_bstart[t][tid] = start;
        if (tid == 0) g_bstart[t][NBINS] = M_BOX;
        #pragma unroll
        for (int j = 0; j < 8; ++j) {
            int pos = atomicAdd(&cnt[bin[j]], 1);
            g_sbox[t][pos]   = box[j];
            g_snarea[t][pos] = -((box[j].z - box[j].x) * (box[j].w - box[j].y));
        }
    } else {
        g_pstart[tid] = start;
        if (tid == 0) g_pstart[NBINS] = N_PRED;
        #pragma unroll
        for (int j = 0; j < 8; ++j) {
            int pos = atomicAdd(&cnt[bin[j]], 1);
            g_pbox[pos] = box[j];
            g_perm[pos] = (j >> 2) * 1024 + tid + (j & 3) * 256;
        }
    }
}

// ---------------------------------------------------------------------------
// match: CTA = (half, pred-y-row yr, run t). Loads the contiguous box slab
// for rows [yr-2, yr+2] into smem, then TWO threads per pred (even/odd lanes
// split the boxes by parity; exact-max combine via shfl). All 128 threads
// carry work. Outside-window boxes can't match (inter <= 0 < thr).
// ---------------------------------------------------------------------------
__global__ __launch_bounds__(128)
void match_kernel(float* __restrict__ out)
{
    __shared__ float4 sbox[CAP];
    __shared__ float  snarea[CAP];
    __shared__ int    sbs[5 * GB + 1];

    const int tid  = threadIdx.x;
    const int half = blockIdx.x;
    const int yr   = blockIdx.y;
    const int t    = blockIdx.z;

    const int r0 = max(yr - 2, 0), r1 = min(yr + 2, GB - 1);
    const int bin_lo = r0 * GB, bin_hi = (r1 + 1) * GB;
    const int nbs = bin_hi - bin_lo + 1;

    const int base = __ldg(&g_bstart[t][bin_lo]);
    const int endi = __ldg(&g_bstart[t][bin_hi]);
    const int n    = endi - base;

    for (int i = tid; i < nbs; i += 128) sbs[i] = g_bstart[t][bin_lo + i];
    const int ncap = min(n, CAP);
    for (int i = tid; i < ncap; i += 128) {
        sbox[i]   = g_sbox[t][base + i];
        snarea[i] = g_snarea[t][base + i];
    }
    __syncthreads();

    const int ps = g_pstart[yr * GB], pe = g_pstart[(yr + 1) * GB];
    const int mid = (ps + pe) >> 1;
    const int seg_s = half ? mid : ps;
    const int seg_e = half ? pe  : mid;
    const bool all_smem = (n <= CAP);   // always true for uniform data
    const int sub = tid & 1;            // which half of the boxes this lane scans

    // warp-uniform outer loop so the full-mask shfl below is always safe
    for (int b0 = seg_s; b0 < seg_e; b0 += 64) {
        const int slot = b0 + (tid >> 1);
        const bool active = (slot < seg_e);

        float best = -1e30f, thr = 1e30f;
        int p = 0;
        if (active) {
            const float4 a = g_pbox[slot];
            p = g_perm[slot];
            thr = (a.z - a.x) * (a.w - a.y) + EPS_F;

            const int xb0 = bin1d(a.x - WH_MAX), xb1 = bin1d(a.z);
            const int yb0 = max(bin1d(a.y - WH_MAX), r0);
            const int yb1 = min(bin1d(a.w), r1);

            if (all_smem) {
                for (int yb = yb0; yb <= yb1; ++yb) {
                    const int rb = yb * GB - bin_lo;
                    const int s  = sbs[rb + xb0] - base;
                    const int e  = sbs[rb + xb1 + 1] - base;
                    #pragma unroll 4
                    for (int m = s + sub; m < e; m += 2) {
                        float4 b  = sbox[m];
                        float ix1 = fmaxf(a.x, b.x);
                        float iy1 = fmaxf(a.y, b.y);
                        float ix2 = fminf(a.z, b.z);
                        float iy2 = fminf(a.w, b.w);
                        float dx  = fmaxf(ix2 - ix1, 0.0f);
                        float dy  = iy2 - iy1;      // dy<0 => inter<=0 < thr
                        best = fmaxf(best, fmaf(3.0f, dx * dy, snarea[m]));
                    }
                    if (best > thr) break;
                }
            } else {                                 // safety fallback (gmem)
                for (int yb = yb0; yb <= yb1; ++yb) {
                    const int rb = yb * GB - bin_lo;
                    const int s  = sbs[rb + xb0];
                    const int e  = sbs[rb + xb1 + 1];
                    for (int m = s + sub; m < e; m += 2) {
                        float4 b  = g_sbox[t][m];
                        float na  = g_snarea[t][m];
                        float ix1 = fmaxf(a.x, b.x);
                        float iy1 = fmaxf(a.y, b.y);
                        float ix2 = fminf(a.z, b.z);
                        float iy2 = fminf(a.w, b.w);
                        float dx  = fmaxf(ix2 - ix1, 0.0f);
                        float dy  = iy2 - iy1;
                        best = fmaxf(best, fmaf(3.0f, dx * dy, na));
                    }
                    if (best > thr) break;
                }
            }
        }

        // exact max-combine across the lane pair (max is order-independent)
        best = fmaxf(best, __shfl_xor_sync(0xffffffffu, best, 1));

        // 16 adds of exactly 1/16: order-independent & exact -> deterministic
        if (active && sub == 0 && best > thr)
            atomicAdd(&out[p], 1.0f / (float)T_RUNS);
    }
}

extern "C" void kernel_launch(void* const* d_in, const int* in_sizes, int n_in,
                              void* d_out, int out_size)
{
    const float* pred          = (const float*)d_in[0]; // [2048, 6]
    const float* dropout_preds = (const float*)d_in[1]; // [16, 2048, 6]
    // d_in[2] (dropout_cls_confs) unused by the reference computation.
    float* out = (float*)d_out;                          // [2048]

    prep_kernel<<<T_RUNS + 1, 256>>>(pred, dropout_preds, out);
    match_kernel<<<dim3(2, GB, T_RUNS), 128>>>(out);
}

// round 6
// speedup vs baseline: 1.2301x; 1.2301x over previous
#include <cuda_runtime.h>
#include <cuda_bf16.h>

#define N_PRED 2048
#define T_RUNS 16
#define M_BOX  2048
#define EPS_F  1e-7f

#define GB      16
#define NBINS   (GB*GB)
#define BIN_ORG (-28.0f)
#define BIN_INV (1.0f/42.0f)
#define WH_MAX  55.0f          // box w,h in [5,55)
#define CAP     1280           // smem slab capacity (5 rows avg ~640)

// ---- device scratch (no allocations allowed) ----
__device__ float4 g_sbox[T_RUNS][M_BOX];      // binned boxes (x1,y1,x2,y2)
__device__ int    g_bstart[T_RUNS][NBINS+1];  // box bin prefix offsets per run
__device__ float4 g_pbox[N_PRED];             // pred boxes, bin-sorted
__device__ int    g_perm[N_PRED];             // sorted slot -> original pred idx
__device__ int    g_pstart[NBINS+1];          // pred bin prefix offsets

__device__ __forceinline__ int bin1d(float v) {
    int b = (int)floorf((v - BIN_ORG) * BIN_INV);
    return min(max(b, 0), GB - 1);
}

// ---------------------------------------------------------------------------
// prep: blocks 0..15 counting-sort run t's boxes; block 16 sorts preds,
// writes g_pstart, zeroes out. 512 threads, 4 boxes each (direct loads —
// the R5 smem staging experiment regressed). Bins owned by tid<256.
// ---------------------------------------------------------------------------
__global__ __launch_bounds__(512)
void prep_kernel(const float* __restrict__ pred,
                 const float* __restrict__ dropout_preds,
                 float* __restrict__ out)
{
    __shared__ int cnt[NBINS];
    __shared__ int wsum[8];
    const int tid  = threadIdx.x;
    const int lane = tid & 31, wid = tid >> 5;
    const bool is_box_block = (blockIdx.x < T_RUNS);

    if (tid < NBINS) cnt[tid] = 0;
    __syncthreads();

    // ---- count ----
    float4 box[4];
    int    bin[4];
    if (is_box_block) {
        const float* src = dropout_preds + (size_t)blockIdx.x * M_BOX * 6;
        #pragma unroll
        for (int k = 0; k < M_BOX / 512; ++k) {
            const float* b6 = src + (tid + k * 512) * 6;
            box[k] = make_float4(b6[0], b6[1], b6[2], b6[3]);
            bin[k] = bin1d(box[k].y) * GB + bin1d(box[k].x);
            atomicAdd(&cnt[bin[k]], 1);
        }
    } else {
        #pragma unroll
        for (int k = 0; k < N_PRED / 512; ++k) {
            int p = tid + k * 512;
            const float* a = pred + p * 6;
            box[k] = make_float4(a[0], a[1], a[2], a[3]);
            bin[k] = bin1d(box[k].y) * GB + bin1d(box[k].x);
            atomicAdd(&cnt[bin[k]], 1);
            out[p] = 0.0f;        // out is poisoned; zero before match
        }
    }
    __syncthreads();

    // ---- exclusive scan over 256 bins (first 8 warps) ----
    int start = 0;
    if (tid < NBINS) {
        int v = cnt[tid];
        int inc = v;
        #pragma unroll
        for (int o = 1; o < 32; o <<= 1) {
            int n = __shfl_up_sync(0xffffffffu, inc, o);
            if (lane >= o) inc += n;
        }
        if (lane == 31) wsum[wid] = inc;
        start = inc - v;
    }
    __syncthreads();
    if (wid == 0) {
        int w = (lane < 8) ? wsum[lane] : 0;
        int wi = w;
        #pragma unroll
        for (int o = 1; o < 8; o <<= 1) {
            int n = __shfl_up_sync(0xffffffffu, wi, o);
            if (lane >= o) wi += n;
        }
        if (lane < 8) wsum[lane] = wi - w;   // exclusive warp offsets
    }
    __syncthreads();
    if (tid < NBINS) {
        start += wsum[wid];
        cnt[tid] = start;                    // running scatter offsets
    }
    __syncthreads();

    // ---- scatter ----
    if (is_box_block) {
        const int t = blockIdx.x;
        if (tid < NBINS) g_bstart[t][tid] = start;
        if (tid == 0)    g_bstart[t][NBINS] = M_BOX;
        #pragma unroll
        for (int k = 0; k < M_BOX / 512; ++k) {
            int pos = atomicAdd(&cnt[bin[k]], 1);
            g_sbox[t][pos] = box[k];
        }
    } else {
        if (tid < NBINS) g_pstart[tid] = start;
        if (tid == 0)    g_pstart[NBINS] = N_PRED;
        #pragma unroll
        for (int k = 0; k < N_PRED / 512; ++k) {
            int pos = atomicAdd(&cnt[bin[k]], 1);
            g_pbox[pos] = box[k];
            g_perm[pos] = tid + k * 512;
        }
    }
}

#define IOU_STEP(BOX, NA, ACC)                                   \
    {   float4 b  = (BOX);                                       \
        float ix1 = fmaxf(a.x, b.x);                             \
        float iy1 = fmaxf(a.y, b.y);                             \
        float ix2 = fminf(a.z, b.z);                             \
        float iy2 = fminf(a.w, b.w);                             \
        float dx  = fmaxf(ix2 - ix1, 0.0f);                      \
        float dy  = iy2 - iy1;   /* dy<0 => inter<=0 < thr */    \
        ACC = fmaxf(ACC, fmaf(3.0f, dx * dy, (NA))); }

// ---------------------------------------------------------------------------
// match: CTA = (pred-y-row yr, run t), 256 threads. One fill of the rows
// [yr-2, yr+2] slab (~640 boxes, -areaB computed during fill), then TWO
// threads per pred with TWO independent accumulators each (2 LDS/fp chains
// in flight). Exact max-combines keep the matched set identical.
// ---------------------------------------------------------------------------
__global__ __launch_bounds__(256)
void match_kernel(float* __restrict__ out)
{
    __shared__ float4 sbox[CAP];
    __shared__ float  snarea[CAP];
    __shared__ int    sbs[5 * GB + 1];

    const int tid = threadIdx.x;
    const int yr  = blockIdx.x;
    const int t   = blockIdx.y;

    const int r0 = max(yr - 2, 0), r1 = min(yr + 2, GB - 1);
    const int bin_lo = r0 * GB, bin_hi = (r1 + 1) * GB;
    const int nbs = bin_hi - bin_lo + 1;

    const int base = __ldg(&g_bstart[t][bin_lo]);
    const int endi = __ldg(&g_bstart[t][bin_hi]);
    const int n    = endi - base;

    if (tid < nbs) sbs[tid] = g_bstart[t][bin_lo + tid];
    const int ncap = min(n, CAP);
    for (int i = tid; i < ncap; i += 256) {
        float4 b  = g_sbox[t][base + i];
        sbox[i]   = b;
        snarea[i] = -((b.z - b.x) * (b.w - b.y));
    }
    __syncthreads();

    const int ps = g_pstart[yr * GB], pe = g_pstart[(yr + 1) * GB];
    const bool all_smem = (n <= CAP);   // always true for uniform data
    const int sub = tid & 1;            // parity half of boxes for this lane

    for (int b0 = ps; b0 < pe; b0 += 128) {
        const int slot = b0 + (tid >> 1);
        const bool active = (slot < pe);

        float best0 = -1e30f, best1 = -1e30f, thr = 1e30f;
        int p = 0;
        if (active) {
            const float4 a = g_pbox[slot];
            p = g_perm[slot];
            thr = (a.z - a.x) * (a.w - a.y) + EPS_F;

            const int xb0 = bin1d(a.x - WH_MAX), xb1 = bin1d(a.z);
            const int yb0 = max(bin1d(a.y - WH_MAX), r0);
            const int yb1 = min(bin1d(a.w), r1);

            if (all_smem) {
                for (int yb = yb0; yb <= yb1; ++yb) {
                    const int rb = yb * GB - bin_lo;
                    const int s  = sbs[rb + xb0] - base;
                    const int e  = sbs[rb + xb1 + 1] - base;
                    int m = s + sub;
                    for (; m + 2 < e; m += 4) {          // 2 chains in flight
                        IOU_STEP(sbox[m],     snarea[m],     best0);
                        IOU_STEP(sbox[m + 2], snarea[m + 2], best1);
                    }
                    if (m < e) IOU_STEP(sbox[m], snarea[m], best0);
                    if (fmaxf(best0, best1) > thr) break;
                }
            } else {                                     // safety fallback
                for (int yb = yb0; yb <= yb1; ++yb) {
                    const int rb = yb * GB - bin_lo;
                    const int s  = sbs[rb + xb0];
                    const int e  = sbs[rb + xb1 + 1];
                    for (int m = s + sub; m < e; m += 2) {
                        float4 bb = g_sbox[t][m];
                        float na  = -((bb.z - bb.x) * (bb.w - bb.y));
                        IOU_STEP(bb, na, best0);
                    }
                    if (fmaxf(best0, best1) > thr) break;
                }
            }
        }

        float best = fmaxf(best0, best1);                // exact combines
        best = fmaxf(best, __shfl_xor_sync(0xffffffffu, best, 1));

        // 16 adds of exactly 1/16: order-independent & exact -> deterministic
        if (active && sub == 0 && best > thr)
            atomicAdd(&out[p], 1.0f / (float)T_RUNS);
    }
}

extern "C" void kernel_launch(void* const* d_in, const int* in_sizes, int n_in,
                              void* d_out, int out_size)
{
    const float* pred          = (const float*)d_in[0]; // [2048, 6]
    const float* dropout_preds = (const float*)d_in[1]; // [16, 2048, 6]
    // d_in[2] (dropout_cls_confs) unused by the reference computation.
    float* out = (float*)d_out;                          // [2048]

    prep_kernel<<<T_RUNS + 1, 512>>>(pred, dropout_preds, out);
    match_kernel<<<dim3(GB, T_RUNS), 256>>>(out);
}